// round 2
// baseline (speedup 1.0000x reference)
#include <cuda_runtime.h>
#include <math.h>

// Problem constants (fixed shapes: L=5, B=8, n=1024, d=64)
#define LNUM 5
#define BNUM 8
#define NLB  (LNUM * BNUM)       // 40
#define N    1024
#define D    64
#define S    8                   // n-dim splits per (l,b)
#define ROWS (N / S)             // 128 rows per block
#define TR   64                  // smem tile rows
#define GSZ  (D * D)             // 4096
#define STRIDE (3 * GSZ + 2 * D) // per-block scratch: XX, YY, XY, sx, sy

__device__ float g_part[NLB * S * STRIDE];   // ~15.9 MB scratch
__device__ float g_ratio[NLB];

// ---------------------------------------------------------------------------
// Kernel A: per (l,b,chunk) partial Grams XtX, YtY, XtY (64x64 each) + column
// sums over a 128-row chunk. 256 threads, 4x4 register microtile.
// ---------------------------------------------------------------------------
__global__ void __launch_bounds__(256, 2) cka_partial_kernel(
    const float* __restrict__ X, const float* __restrict__ Y)
{
    __shared__ float Xs[TR * D];
    __shared__ float Ys[TR * D];
    __shared__ float red[256];

    const int tid = threadIdx.x;
    const int tx = tid & 15;        // i-side: columns {tx, tx+16, tx+32, tx+48}
    const int ty = tid >> 4;        // j-side: columns {ty, ty+16, ty+32, ty+48}
    const int lb = blockIdx.x / S;
    const int chunk = blockIdx.x % S;

    const float* xb = X + (size_t)lb * N * D + (size_t)chunk * ROWS * D;
    const float* yb = Y + (size_t)lb * N * D + (size_t)chunk * ROWS * D;

    float aXX[4][4] = {};
    float aYY[4][4] = {};
    float aXY[4][4] = {};
    float csx = 0.f, csy = 0.f;
    const int col  = tid & 63;      // column-sum ownership
    const int rgrp = tid >> 6;      // 4 row groups of 16 rows

    for (int t = 0; t < ROWS / TR; ++t) {
        __syncthreads();   // protect smem from previous iteration's readers
        // cooperative vectorized tile load: TR*D floats = 1024 float4 each
        const float4* xs4 = (const float4*)(xb + (size_t)t * TR * D);
        const float4* ys4 = (const float4*)(yb + (size_t)t * TR * D);
        float4* Xs4 = (float4*)Xs;
        float4* Ys4 = (float4*)Ys;
        #pragma unroll
        for (int k = 0; k < (TR * D / 4) / 256; ++k) {
            Xs4[tid + 256 * k] = xs4[tid + 256 * k];
            Ys4[tid + 256 * k] = ys4[tid + 256 * k];
        }
        __syncthreads();

        #pragma unroll 4
        for (int r = 0; r < TR; ++r) {
            float xi[4], yi[4], xj[4], yj[4];
            #pragma unroll
            for (int k = 0; k < 4; ++k) {
                xi[k] = Xs[r * D + tx + 16 * k];
                yi[k] = Ys[r * D + tx + 16 * k];
                xj[k] = Xs[r * D + ty + 16 * k];
                yj[k] = Ys[r * D + ty + 16 * k];
            }
            #pragma unroll
            for (int a = 0; a < 4; ++a)
                #pragma unroll
                for (int b2 = 0; b2 < 4; ++b2) {
                    aXX[a][b2] = fmaf(xi[a], xj[b2], aXX[a][b2]);
                    aYY[a][b2] = fmaf(yi[a], yj[b2], aYY[a][b2]);
                    aXY[a][b2] = fmaf(xi[a], yj[b2], aXY[a][b2]);
                }
        }

        // column-sum partials over this tile (conflict-free: consecutive cols)
        #pragma unroll
        for (int rr = 0; rr < TR / 4; ++rr) {
            int r = rgrp * (TR / 4) + rr;
            csx += Xs[r * D + col];
            csy += Ys[r * D + col];
        }
    }

    float* out = g_part + (size_t)blockIdx.x * STRIDE;

    // reduce column sums (4 partials per column)
    red[tid] = csx;
    __syncthreads();
    if (tid < 64)
        out[3 * GSZ + tid] = red[tid] + red[tid + 64] + red[tid + 128] + red[tid + 192];
    __syncthreads();
    red[tid] = csy;
    __syncthreads();
    if (tid < 64)
        out[3 * GSZ + 64 + tid] = red[tid] + red[tid + 64] + red[tid + 128] + red[tid + 192];

    // write partial Grams
    #pragma unroll
    for (int a = 0; a < 4; ++a)
        #pragma unroll
        for (int b2 = 0; b2 < 4; ++b2) {
            int i = tx + 16 * a;
            int j = ty + 16 * b2;
            out[i * D + j]           = aXX[a][b2];
            out[GSZ + i * D + j]     = aYY[a][b2];
            out[2 * GSZ + i * D + j] = aXY[a][b2];
        }
}

// ---------------------------------------------------------------------------
// Kernel B: per (l,b) reduce S partials, apply rank-1 centering correction,
// Frobenius-square-reduce -> ratio[lb].
// ---------------------------------------------------------------------------
__global__ void __launch_bounds__(256) cka_finalize_kernel()
{
    const int lb = blockIdx.x;
    const int tid = threadIdx.x;
    __shared__ float sx[D], sy[D];
    __shared__ float red[256];

    const float* base = g_part + (size_t)lb * S * STRIDE;

    if (tid < D) {
        float ax = 0.f, ay = 0.f;
        #pragma unroll
        for (int s = 0; s < S; ++s) {
            ax += base[(size_t)s * STRIDE + 3 * GSZ + tid];
            ay += base[(size_t)s * STRIDE + 3 * GSZ + 64 + tid];
        }
        sx[tid] = ax;
        sy[tid] = ay;
    }
    __syncthreads();

    float sXX = 0.f, sYY = 0.f, sXY = 0.f;
    const float inv_n = 1.0f / (float)N;
    #pragma unroll
    for (int k = 0; k < GSZ / 256; ++k) {
        int idx = tid + 256 * k;
        int i = idx >> 6;
        int j = idx & 63;
        float gxx = 0.f, gyy = 0.f, gxy = 0.f;
        #pragma unroll
        for (int s = 0; s < S; ++s) {
            const float* p = base + (size_t)s * STRIDE;
            gxx += p[idx];
            gyy += p[GSZ + idx];
            gxy += p[2 * GSZ + idx];
        }
        gxx -= sx[i] * sx[j] * inv_n;
        gyy -= sy[i] * sy[j] * inv_n;
        gxy -= sx[i] * sy[j] * inv_n;
        sXX = fmaf(gxx, gxx, sXX);
        sYY = fmaf(gyy, gyy, sYY);
        sXY = fmaf(gxy, gxy, sXY);
    }

    // sequential block reductions
    float tXX, tYY, tXY;
    red[tid] = sXX;
    __syncthreads();
    for (int off = 128; off > 0; off >>= 1) {
        if (tid < off) red[tid] += red[tid + off];
        __syncthreads();
    }
    tXX = red[0];
    __syncthreads();

    red[tid] = sYY;
    __syncthreads();
    for (int off = 128; off > 0; off >>= 1) {
        if (tid < off) red[tid] += red[tid + off];
        __syncthreads();
    }
    tYY = red[0];
    __syncthreads();

    red[tid] = sXY;
    __syncthreads();
    for (int off = 128; off > 0; off >>= 1) {
        if (tid < off) red[tid] += red[tid + off];
        __syncthreads();
    }
    tXY = red[0];

    if (tid == 0) {
        g_ratio[lb] = fabsf(tXY) / (sqrtf(tXX) * sqrtf(tYY));
    }
}

// ---------------------------------------------------------------------------
// Kernel C: final scalar loss = mean_l( -log( mean_b ratio + eps ) )
// ---------------------------------------------------------------------------
__global__ void cka_final_kernel(float* __restrict__ out)
{
    if (threadIdx.x == 0 && blockIdx.x == 0) {
        float loss = 0.f;
        #pragma unroll
        for (int l = 0; l < LNUM; ++l) {
            float m = 0.f;
            #pragma unroll
            for (int b = 0; b < BNUM; ++b)
                m += g_ratio[l * BNUM + b];
            m *= (1.0f / (float)BNUM);
            loss += -logf(m + 1e-8f);
        }
        out[0] = loss * (1.0f / (float)LNUM);
    }
}

extern "C" void kernel_launch(void* const* d_in, const int* in_sizes, int n_in,
                              void* d_out, int out_size)
{
    const float* teacher = (const float*)d_in[0];
    const float* student = (const float*)d_in[1];
    float* out = (float*)d_out;

    cka_partial_kernel<<<NLB * S, 256>>>(teacher, student);
    cka_finalize_kernel<<<NLB, 256>>>();
    cka_final_kernel<<<1, 32>>>(out);
}

// round 3
// speedup vs baseline: 1.5725x; 1.5725x over previous
#include <cuda_runtime.h>
#include <math.h>

// Problem constants (fixed shapes: L=5, B=8, n=1024, d=64)
#define LNUM 5
#define BNUM 8
#define NLB  (LNUM * BNUM)       // 40
#define N    1024
#define D    64
#define S    8                   // n-dim splits per (l,b)
#define ROWS (N / S)             // 128 rows per chunk
#define TR   64                  // smem tile rows
#define GSZ  (D * D)             // 4096
#define STRIDE (3 * GSZ + 2 * D) // per-chunk scratch: XX, YY, XY, sx, sy

__device__ float g_part[NLB * S * STRIDE];   // ~15.9 MB scratch
__device__ float g_sums[NLB * 8 * 3];        // per (lb, slice): sXX, sYY, sXY

// ---------------------------------------------------------------------------
// Kernel A: per (l,b,chunk,jhalf) partial Grams. 128 threads, 4x4 microtile
// with contiguous columns -> LDS.128 operand loads. Each block computes a
// 64x32 j-half of XtX, YtY, XtY over a 128-row chunk. jc==0 blocks also
// produce the column sums.
// grid = NLB * S * 2 = 640 blocks.
// ---------------------------------------------------------------------------
__global__ void __launch_bounds__(128, 5) cka_partial_kernel(
    const float* __restrict__ X, const float* __restrict__ Y)
{
    __shared__ float Xs[TR * D];
    __shared__ float Ys[TR * D];
    __shared__ float red[128];

    const int tid = threadIdx.x;
    const int tx = tid & 15;        // i-cols: 4*tx .. 4*tx+3 (contiguous)
    const int ty = tid >> 4;        // 0..7 -> j-cols: 32*jc + 4*ty .. +3
    const int bx = blockIdx.x;
    const int lb = bx >> 4;
    const int rem = bx & 15;
    const int chunk = rem >> 1;
    const int jc = rem & 1;

    const float* xb = X + (size_t)lb * N * D + (size_t)chunk * ROWS * D;
    const float* yb = Y + (size_t)lb * N * D + (size_t)chunk * ROWS * D;

    float aXX[4][4] = {};
    float aYY[4][4] = {};
    float aXY[4][4] = {};
    float csx = 0.f, csy = 0.f;
    const int col  = tid & 63;      // column-sum ownership
    const int half = tid >> 6;      // 2 row groups of 32

    #pragma unroll
    for (int t = 0; t < ROWS / TR; ++t) {
        __syncthreads();   // protect smem from previous iteration's readers
        // cooperative vectorized tile load: TR*D floats = 1024 float4
        const float4* xs4 = (const float4*)(xb + t * TR * D);
        const float4* ys4 = (const float4*)(yb + t * TR * D);
        float4* Xs4 = (float4*)Xs;
        float4* Ys4 = (float4*)Ys;
        #pragma unroll
        for (int k = 0; k < (TR * D / 4) / 128; ++k) {
            Xs4[tid + 128 * k] = xs4[tid + 128 * k];
            Ys4[tid + 128 * k] = ys4[tid + 128 * k];
        }
        __syncthreads();

        #pragma unroll 8
        for (int r = 0; r < TR; ++r) {
            const float4* Xr = (const float4*)(Xs + r * D);
            const float4* Yr = (const float4*)(Ys + r * D);
            float4 xi = Xr[tx];
            float4 yi = Yr[tx];
            float4 xj = Xr[8 * jc + ty];
            float4 yj = Yr[8 * jc + ty];
            float xiA[4] = {xi.x, xi.y, xi.z, xi.w};
            float yiA[4] = {yi.x, yi.y, yi.z, yi.w};
            float xjA[4] = {xj.x, xj.y, xj.z, xj.w};
            float yjA[4] = {yj.x, yj.y, yj.z, yj.w};
            #pragma unroll
            for (int a = 0; a < 4; ++a)
                #pragma unroll
                for (int b2 = 0; b2 < 4; ++b2) {
                    aXX[a][b2] = fmaf(xiA[a], xjA[b2], aXX[a][b2]);
                    aYY[a][b2] = fmaf(yiA[a], yjA[b2], aYY[a][b2]);
                    aXY[a][b2] = fmaf(xiA[a], yjA[b2], aXY[a][b2]);
                }
        }

        // column-sum partials (only jc==0 blocks; uniform branch)
        if (jc == 0) {
            #pragma unroll 8
            for (int rr = 0; rr < TR / 2; ++rr) {
                int r = half * (TR / 2) + rr;
                csx += Xs[r * D + col];
                csy += Ys[r * D + col];
            }
        }
    }

    float* out = g_part + (size_t)(lb * S + chunk) * STRIDE;

    if (jc == 0) {
        red[tid] = csx;
        __syncthreads();
        if (tid < 64) out[3 * GSZ + tid] = red[tid] + red[tid + 64];
        __syncthreads();
        red[tid] = csy;
        __syncthreads();
        if (tid < 64) out[3 * GSZ + 64 + tid] = red[tid] + red[tid + 64];
    }

    // float4 stores: lanes (tx, ty even/odd) pair into contiguous 32B sectors
    #pragma unroll
    for (int a = 0; a < 4; ++a) {
        int i = 4 * tx + a;
        int j = 32 * jc + 4 * ty;
        float4 vxx = {aXX[a][0], aXX[a][1], aXX[a][2], aXX[a][3]};
        float4 vyy = {aYY[a][0], aYY[a][1], aYY[a][2], aYY[a][3]};
        float4 vxy = {aXY[a][0], aXY[a][1], aXY[a][2], aXY[a][3]};
        *(float4*)(out + i * D + j)           = vxx;
        *(float4*)(out + GSZ + i * D + j)     = vyy;
        *(float4*)(out + 2 * GSZ + i * D + j) = vxy;
    }
}

// ---------------------------------------------------------------------------
// Kernel B: per (lb, slice-of-8) reduce S chunk-partials, apply rank-1
// centering correction, partial Frobenius-square-reduce.
// grid = NLB * 8 = 320 blocks, 128 threads, float4 loads.
// ---------------------------------------------------------------------------
__global__ void __launch_bounds__(128) cka_reduce_kernel()
{
    const int lb = blockIdx.x >> 3;
    const int slice = blockIdx.x & 7;
    const int tid = threadIdx.x;
    __shared__ float sx[D], sy[D];
    __shared__ float red[128];

    const float* base = g_part + (size_t)lb * S * STRIDE;

    if (tid < 64) {
        float ax = 0.f, ay = 0.f;
        #pragma unroll
        for (int s = 0; s < S; ++s) {
            ax += base[s * STRIDE + 3 * GSZ + tid];
            ay += base[s * STRIDE + 3 * GSZ + 64 + tid];
        }
        sx[tid] = ax;
        sy[tid] = ay;
    }
    __syncthreads();

    const float inv_n = 1.0f / (float)N;
    const int f4i = slice * 128 + tid;   // float4 index within a 64x64 matrix
    const int i  = f4i >> 4;             // row
    const int jb = (f4i & 15) * 4;       // first column of the float4

    const float sxi = sx[i] * inv_n;
    const float syi = sy[i] * inv_n;
    const float4 sxj = *(const float4*)&sx[jb];
    const float4 syj = *(const float4*)&sy[jb];

    float4 gxx = {0,0,0,0}, gyy = {0,0,0,0}, gxy = {0,0,0,0};
    #pragma unroll
    for (int s = 0; s < S; ++s) {
        const float4* p = (const float4*)(base + (size_t)s * STRIDE);
        float4 v;
        v = p[f4i];
        gxx.x += v.x; gxx.y += v.y; gxx.z += v.z; gxx.w += v.w;
        v = p[1024 + f4i];
        gyy.x += v.x; gyy.y += v.y; gyy.z += v.z; gyy.w += v.w;
        v = p[2048 + f4i];
        gxy.x += v.x; gxy.y += v.y; gxy.z += v.z; gxy.w += v.w;
    }

    gxx.x -= sxi * sxj.x; gxx.y -= sxi * sxj.y; gxx.z -= sxi * sxj.z; gxx.w -= sxi * sxj.w;
    gyy.x -= syi * syj.x; gyy.y -= syi * syj.y; gyy.z -= syi * syj.z; gyy.w -= syi * syj.w;
    gxy.x -= sxi * syj.x; gxy.y -= sxi * syj.y; gxy.z -= sxi * syj.z; gxy.w -= sxi * syj.w;

    float vXX = gxx.x*gxx.x + gxx.y*gxx.y + gxx.z*gxx.z + gxx.w*gxx.w;
    float vYY = gyy.x*gyy.x + gyy.y*gyy.y + gyy.z*gyy.z + gyy.w*gyy.w;
    float vXY = gxy.x*gxy.x + gxy.y*gxy.y + gxy.z*gxy.z + gxy.w*gxy.w;

    float* gs = g_sums + (size_t)(lb * 8 + slice) * 3;

    red[tid] = vXX;
    __syncthreads();
    for (int off = 64; off > 0; off >>= 1) {
        if (tid < off) red[tid] += red[tid + off];
        __syncthreads();
    }
    if (tid == 0) gs[0] = red[0];
    __syncthreads();

    red[tid] = vYY;
    __syncthreads();
    for (int off = 64; off > 0; off >>= 1) {
        if (tid < off) red[tid] += red[tid + off];
        __syncthreads();
    }
    if (tid == 0) gs[1] = red[0];
    __syncthreads();

    red[tid] = vXY;
    __syncthreads();
    for (int off = 64; off > 0; off >>= 1) {
        if (tid < off) red[tid] += red[tid + off];
        __syncthreads();
    }
    if (tid == 0) gs[2] = red[0];
}

// ---------------------------------------------------------------------------
// Kernel C: final scalar loss = mean_l( -log( mean_b ratio + eps ) )
// ---------------------------------------------------------------------------
__global__ void cka_final_kernel(float* __restrict__ out)
{
    __shared__ float ratio[NLB];
    const int tid = threadIdx.x;
    if (tid < NLB) {
        float txx = 0.f, tyy = 0.f, txy = 0.f;
        #pragma unroll
        for (int s2 = 0; s2 < 8; ++s2) {
            const float* g = g_sums + (size_t)(tid * 8 + s2) * 3;
            txx += g[0];
            tyy += g[1];
            txy += g[2];
        }
        ratio[tid] = fabsf(txy) / (sqrtf(txx) * sqrtf(tyy));
    }
    __syncthreads();
    if (tid == 0) {
        float loss = 0.f;
        #pragma unroll
        for (int l = 0; l < LNUM; ++l) {
            float m = 0.f;
            #pragma unroll
            for (int b = 0; b < BNUM; ++b)
                m += ratio[l * BNUM + b];
            m *= (1.0f / (float)BNUM);
            loss += -logf(m + 1e-8f);
        }
        out[0] = loss * (1.0f / (float)LNUM);
    }
}

extern "C" void kernel_launch(void* const* d_in, const int* in_sizes, int n_in,
                              void* d_out, int out_size)
{
    const float* teacher = (const float*)d_in[0];
    const float* student = (const float*)d_in[1];
    float* out = (float*)d_out;

    cka_partial_kernel<<<NLB * S * 2, 128>>>(teacher, student);
    cka_reduce_kernel<<<NLB * 8, 128>>>();
    cka_final_kernel<<<1, 64>>>(out);
}

// round 5
// speedup vs baseline: 1.6556x; 1.0528x over previous
#include <cuda_runtime.h>
#include <math.h>

// Problem constants (fixed shapes: L=5, B=8, n=1024, d=64)
#define LNUM 5
#define BNUM 8
#define NLB  (LNUM * BNUM)       // 40
#define N    1024
#define D    64
#define S    8                   // n-dim splits per (l,b)
#define ROWS (N / S)             // 128 rows per chunk
#define TR   64                  // smem tile rows
#define GSZ  (D * D)             // 4096
#define STRIDE (3 * GSZ + 2 * D) // per-chunk scratch: XX, YY, XY, sx, sy

__device__ float g_part[NLB * S * STRIDE];   // ~15.9 MB scratch
__device__ float g_sums[NLB * 8 * 3];        // per (lb, slice): sXX, sYY, sXY

typedef unsigned long long u64;

// packed f32x2 FMA: acc.lo += a.lo*b.lo ; acc.hi += a.hi*b.hi
#define FMA2(acc, a, b) \
    asm("fma.rn.f32x2 %0, %1, %2, %0;" : "+l"(acc) : "l"(a), "l"(b))

static __device__ __forceinline__ u64 bcast2(float v) {
    u64 r;
    asm("mov.b64 %0, {%1, %1};" : "=l"(r) : "f"(v));
    return r;
}

static __device__ __forceinline__ float2 unpk2(u64 v) {
    float2 f;
    asm("mov.b64 {%0, %1}, %2;" : "=f"(f.x), "=f"(f.y) : "l"(v));
    return f;
}

// ---------------------------------------------------------------------------
// Kernel A: per (l,b,chunk,jhalf) partial Grams with packed FFMA2.
// 128 threads; each thread owns a 4(i) x 4(j) microtile where the 4 j-cols
// are two f32x2 lanes. grid = NLB * S * 2 = 640 blocks.
// ---------------------------------------------------------------------------
__global__ void __launch_bounds__(128, 5) cka_partial_kernel(
    const float* __restrict__ X, const float* __restrict__ Y)
{
    __shared__ float Xs[TR * D];
    __shared__ float Ys[TR * D];
    __shared__ float red[128];

    const int tid = threadIdx.x;
    const int tx = tid & 15;        // i-cols: 4*tx .. 4*tx+3 (contiguous)
    const int ty = tid >> 4;        // 0..7 -> j-cols: 32*jc + 4*ty .. +3
    const int bx = blockIdx.x;
    const int lb = bx >> 4;
    const int rem = bx & 15;
    const int chunk = rem >> 1;
    const int jc = rem & 1;

    const float* xb = X + (size_t)lb * N * D + (size_t)chunk * ROWS * D;
    const float* yb = Y + (size_t)lb * N * D + (size_t)chunk * ROWS * D;

    // accumulators: [a][pair], each u64 holds 2 packed f32 j-lanes
    u64 aXX[4][2] = {};
    u64 aYY[4][2] = {};
    u64 aXY[4][2] = {};
    float csx = 0.f, csy = 0.f;
    const int col  = tid & 63;      // column-sum ownership
    const int half = tid >> 6;      // 2 row groups of 32

    #pragma unroll
    for (int t = 0; t < ROWS / TR; ++t) {
        __syncthreads();   // protect smem from previous iteration's readers
        const float4* xs4 = (const float4*)(xb + t * TR * D);
        const float4* ys4 = (const float4*)(yb + t * TR * D);
        float4* Xs4 = (float4*)Xs;
        float4* Ys4 = (float4*)Ys;
        #pragma unroll
        for (int k = 0; k < (TR * D / 4) / 128; ++k) {
            Xs4[tid + 128 * k] = xs4[tid + 128 * k];
            Ys4[tid + 128 * k] = ys4[tid + 128 * k];
        }
        __syncthreads();

        #pragma unroll 8
        for (int r = 0; r < TR; ++r) {
            const float* rowX = Xs + r * D;
            const float* rowY = Ys + r * D;
            // j operands: naturally packed f32 pairs via 16B loads
            double2 xj = ((const double2*)(rowX + 32 * jc))[ty];
            double2 yj = ((const double2*)(rowY + 32 * jc))[ty];
            u64 xj0 = __double_as_longlong(xj.x);
            u64 xj1 = __double_as_longlong(xj.y);
            u64 yj0 = __double_as_longlong(yj.x);
            u64 yj1 = __double_as_longlong(yj.y);
            // i operands: 4 scalars each, broadcast-packed
            float4 xi = ((const float4*)rowX)[tx];
            float4 yi = ((const float4*)rowY)[tx];
            float xiA[4] = {xi.x, xi.y, xi.z, xi.w};
            float yiA[4] = {yi.x, yi.y, yi.z, yi.w};
            #pragma unroll
            for (int a = 0; a < 4; ++a) {
                u64 xb2 = bcast2(xiA[a]);
                u64 yb2 = bcast2(yiA[a]);
                FMA2(aXX[a][0], xb2, xj0);
                FMA2(aXX[a][1], xb2, xj1);
                FMA2(aXY[a][0], xb2, yj0);
                FMA2(aXY[a][1], xb2, yj1);
                FMA2(aYY[a][0], yb2, yj0);
                FMA2(aYY[a][1], yb2, yj1);
            }
        }

        // column-sum partials (only jc==0 blocks; uniform branch)
        if (jc == 0) {
            #pragma unroll 8
            for (int rr = 0; rr < TR / 2; ++rr) {
                int r = half * (TR / 2) + rr;
                csx += Xs[r * D + col];
                csy += Ys[r * D + col];
            }
        }
    }

    float* out = g_part + (size_t)(lb * S + chunk) * STRIDE;

    if (jc == 0) {
        red[tid] = csx;
        __syncthreads();
        if (tid < 64) out[3 * GSZ + tid] = red[tid] + red[tid + 64];
        __syncthreads();
        red[tid] = csy;
        __syncthreads();
        if (tid < 64) out[3 * GSZ + 64 + tid] = red[tid] + red[tid + 64];
    }

    // float4 stores of unpacked accumulator pairs
    #pragma unroll
    for (int a = 0; a < 4; ++a) {
        int i = 4 * tx + a;
        int j = 32 * jc + 4 * ty;
        float2 x0 = unpk2(aXX[a][0]), x1 = unpk2(aXX[a][1]);
        float2 y0 = unpk2(aYY[a][0]), y1 = unpk2(aYY[a][1]);
        float2 z0 = unpk2(aXY[a][0]), z1 = unpk2(aXY[a][1]);
        float4 vxx = {x0.x, x0.y, x1.x, x1.y};
        float4 vyy = {y0.x, y0.y, y1.x, y1.y};
        float4 vxy = {z0.x, z0.y, z1.x, z1.y};
        *(float4*)(out + i * D + j)           = vxx;
        *(float4*)(out + GSZ + i * D + j)     = vyy;
        *(float4*)(out + 2 * GSZ + i * D + j) = vxy;
    }
}

// ---------------------------------------------------------------------------
// Kernel B: per (lb, slice-of-8) reduce S chunk-partials, apply rank-1
// centering correction, partial Frobenius-square-reduce.
// grid = NLB * 8 = 320 blocks, 128 threads, float4 loads.
// ---------------------------------------------------------------------------
__global__ void __launch_bounds__(128) cka_reduce_kernel()
{
    const int lb = blockIdx.x >> 3;
    const int slice = blockIdx.x & 7;
    const int tid = threadIdx.x;
    __shared__ float sx[D], sy[D];
    __shared__ float red[128];

    const float* base = g_part + (size_t)lb * S * STRIDE;

    if (tid < 64) {
        float ax = 0.f, ay = 0.f;
        #pragma unroll
        for (int s = 0; s < S; ++s) {
            ax += base[s * STRIDE + 3 * GSZ + tid];
            ay += base[s * STRIDE + 3 * GSZ + 64 + tid];
        }
        sx[tid] = ax;
        sy[tid] = ay;
    }
    __syncthreads();

    const float inv_n = 1.0f / (float)N;
    const int f4i = slice * 128 + tid;   // float4 index within a 64x64 matrix
    const int i  = f4i >> 4;             // row
    const int jb = (f4i & 15) * 4;       // first column of the float4

    const float sxi = sx[i] * inv_n;
    const float syi = sy[i] * inv_n;
    const float4 sxj = *(const float4*)&sx[jb];
    const float4 syj = *(const float4*)&sy[jb];

    float4 gxx = {0,0,0,0}, gyy = {0,0,0,0}, gxy = {0,0,0,0};
    #pragma unroll
    for (int s = 0; s < S; ++s) {
        const float4* p = (const float4*)(base + (size_t)s * STRIDE);
        float4 v;
        v = p[f4i];
        gxx.x += v.x; gxx.y += v.y; gxx.z += v.z; gxx.w += v.w;
        v = p[1024 + f4i];
        gyy.x += v.x; gyy.y += v.y; gyy.z += v.z; gyy.w += v.w;
        v = p[2048 + f4i];
        gxy.x += v.x; gxy.y += v.y; gxy.z += v.z; gxy.w += v.w;
    }

    gxx.x -= sxi * sxj.x; gxx.y -= sxi * sxj.y; gxx.z -= sxi * sxj.z; gxx.w -= sxi * sxj.w;
    gyy.x -= syi * syj.x; gyy.y -= syi * syj.y; gyy.z -= syi * syj.z; gyy.w -= syi * syj.w;
    gxy.x -= sxi * syj.x; gxy.y -= sxi * syj.y; gxy.z -= sxi * syj.z; gxy.w -= sxi * syj.w;

    float vXX = gxx.x*gxx.x + gxx.y*gxx.y + gxx.z*gxx.z + gxx.w*gxx.w;
    float vYY = gyy.x*gyy.x + gyy.y*gyy.y + gyy.z*gyy.z + gyy.w*gyy.w;
    float vXY = gxy.x*gxy.x + gxy.y*gxy.y + gxy.z*gxy.z + gxy.w*gxy.w;

    float* gs = g_sums + (size_t)(lb * 8 + slice) * 3;

    red[tid] = vXX;
    __syncthreads();
    for (int off = 64; off > 0; off >>= 1) {
        if (tid < off) red[tid] += red[tid + off];
        __syncthreads();
    }
    if (tid == 0) gs[0] = red[0];
    __syncthreads();

    red[tid] = vYY;
    __syncthreads();
    for (int off = 64; off > 0; off >>= 1) {
        if (tid < off) red[tid] += red[tid + off];
        __syncthreads();
    }
    if (tid == 0) gs[1] = red[0];
    __syncthreads();

    red[tid] = vXY;
    __syncthreads();
    for (int off = 64; off > 0; off >>= 1) {
        if (tid < off) red[tid] += red[tid + off];
        __syncthreads();
    }
    if (tid == 0) gs[2] = red[0];
}

// ---------------------------------------------------------------------------
// Kernel C: final scalar loss = mean_l( -log( mean_b ratio + eps ) )
// ---------------------------------------------------------------------------
__global__ void cka_final_kernel(float* __restrict__ out)
{
    __shared__ float ratio[NLB];
    const int tid = threadIdx.x;
    if (tid < NLB) {
        float txx = 0.f, tyy = 0.f, txy = 0.f;
        #pragma unroll
        for (int s2 = 0; s2 < 8; ++s2) {
            const float* g = g_sums + (size_t)(tid * 8 + s2) * 3;
            txx += g[0];
            tyy += g[1];
            txy += g[2];
        }
        ratio[tid] = fabsf(txy) / (sqrtf(txx) * sqrtf(tyy));
    }
    __syncthreads();
    if (tid == 0) {
        float loss = 0.f;
        #pragma unroll
        for (int l = 0; l < LNUM; ++l) {
            float m = 0.f;
            #pragma unroll
            for (int b = 0; b < BNUM; ++b)
                m += ratio[l * BNUM + b];
            m *= (1.0f / (float)BNUM);
            loss += -logf(m + 1e-8f);
        }
        out[0] = loss * (1.0f / (float)LNUM);
    }
}

extern "C" void kernel_launch(void* const* d_in, const int* in_sizes, int n_in,
                              void* d_out, int out_size)
{
    const float* teacher = (const float*)d_in[0];
    const float* student = (const float*)d_in[1];
    float* out = (float*)d_out;

    cka_partial_kernel<<<NLB * S * 2, 128>>>(teacher, student);
    cka_reduce_kernel<<<NLB * 8, 128>>>();
    cka_final_kernel<<<1, 64>>>(out);
}